// round 4
// baseline (speedup 1.0000x reference)
#include <cuda_runtime.h>
#include <cstddef>

// Problem constants (fixed by setup_inputs)
#define BATCH 1024
#define F1 10          // layer-1 fanout
#define F0 25          // layer-0 fanout
#define D 128          // feature dim
#define NROWS1 (BATCH*F1)        // 10240
#define NTOT (BATCH + NROWS1)    // 11264

// Scratch (device globals — no allocations allowed).
__device__ int   g_s1[NROWS1];
__device__ float g_Xself[(size_t)NTOT * D];
__device__ float g_Xneigh[(size_t)NTOT * D];
__device__ float g_N[(size_t)NTOT * 256];
__device__ float g_m1[(size_t)BATCH * 256];
__device__ float g_Y[(size_t)BATCH * 256];

// ---------------------------------------------------------------------------
// K1: level-0 batch nodes: h0 gather, s1 index generation, mean of 10 neighbors
// grid = BATCH blocks x 128 threads
// NOTE: batch_nodes is int32 on device (JAX x64 disabled demotes int64).
// ---------------------------------------------------------------------------
__global__ void k_sample1(const float* __restrict__ features,
                          const int* __restrict__ adj,
                          const int* __restrict__ batch)
{
    int b = blockIdx.x, t = threadIdx.x;
    int s0 = batch[b];
    g_Xself[(size_t)b * D + t] = features[(size_t)s0 * D + t];

    __shared__ int idx[F1];
    if (t < F1) {
        int v = adj[(size_t)s0 * 128 + t];
        idx[t] = v;
        g_s1[b * F1 + t] = v;
    }
    __syncthreads();

    float acc = 0.f;
    #pragma unroll
    for (int j = 0; j < F1; j++)
        acc += features[(size_t)idx[j] * D + t];
    g_Xneigh[(size_t)b * D + t] = acc * (1.f / F1);
}

// ---------------------------------------------------------------------------
// K2: level-1 nodes (10240): h1 gather + mean over 25 level-2 neighbors.
// The big one: 256000 x 512B random row gathers (~131 MB, mostly L2-resident).
// grid = NROWS1 blocks x 128 threads
// ---------------------------------------------------------------------------
__global__ void k_sample2(const float* __restrict__ features,
                          const int* __restrict__ adj)
{
    int i = blockIdx.x, t = threadIdx.x;
    int s = g_s1[i];
    g_Xself[(size_t)(BATCH + i) * D + t] = features[(size_t)s * D + t];

    __shared__ int idx[F0];
    if (t < F0) idx[t] = adj[(size_t)s * 128 + t];
    __syncthreads();

    float acc = 0.f;
    #pragma unroll
    for (int j = 0; j < F0; j++)
        acc += features[(size_t)idx[j] * D + t];
    g_Xneigh[(size_t)(BATCH + i) * D + t] = acc * (1.f / F0);
}

// ---------------------------------------------------------------------------
// Generic half-split GEMM over the scratch globals:
//   Out[r, 0:128]   = act(Xself  @ Wself)
//   Out[r, 128:256] = act(Xneigh @ Wneigh)
// W is [KDIM, 128] row-major. Out row stride 256.
// Block: 256 threads -> COLS columns x ROWS rows tile; weights + X in smem.
// LAYER: 0 -> (g_Xself, g_Xneigh) KDIM=128 -> g_N, ReLU
//        1 -> (g_N rows 0..1023, g_m1) KDIM=256 -> g_Y, identity
// ---------------------------------------------------------------------------
template<int KDIM, int COLS, int ROWS, bool RELU, int LAYER>
__global__ void __launch_bounds__(256)
k_gemm(const float* __restrict__ Wself, const float* __restrict__ Wneigh)
{
    __shared__ __align__(16) float Xs[ROWS * KDIM];
    __shared__ float Ws[KDIM * COLS];

    const int c0 = blockIdx.y * COLS;          // global output column base
    const bool isSelf = (c0 < 128);
    const float* X = (LAYER == 0) ? (isSelf ? g_Xself : g_Xneigh)
                                  : (isSelf ? g_N     : g_m1);
    float* Out = (LAYER == 0) ? g_N : g_Y;
    const float* W = (isSelf ? Wself : Wneigh) + (c0 & 127);
    const int r0 = blockIdx.x * ROWS;
    const int tid = threadIdx.x;

    #pragma unroll 4
    for (int i = tid; i < KDIM * COLS; i += 256)
        Ws[i] = W[(i / COLS) * 128 + (i % COLS)];
    #pragma unroll 4
    for (int i = tid; i < ROWS * KDIM; i += 256)
        Xs[i] = X[(size_t)r0 * KDIM + i];
    __syncthreads();

    constexpr int RG  = 256 / COLS;   // row groups
    constexpr int RPT = ROWS / RG;    // rows per thread
    const int cl = tid % COLS;
    const int rb = (tid / COLS) * RPT;

    float acc[RPT];
    #pragma unroll
    for (int r = 0; r < RPT; r++) acc[r] = 0.f;

    const float4* Xs4 = reinterpret_cast<const float4*>(Xs);
    #pragma unroll 4
    for (int k4 = 0; k4 < KDIM / 4; k4++) {
        float4 xv[RPT];
        #pragma unroll
        for (int r = 0; r < RPT; r++)
            xv[r] = Xs4[(rb + r) * (KDIM / 4) + k4];
        #pragma unroll
        for (int kk = 0; kk < 4; kk++) {
            float w = Ws[(k4 * 4 + kk) * COLS + cl];
            #pragma unroll
            for (int r = 0; r < RPT; r++)
                acc[r] += (&xv[r].x)[kk] * w;
        }
    }

    #pragma unroll
    for (int r = 0; r < RPT; r++) {
        float v = acc[r];
        if (RELU) v = fmaxf(v, 0.f);
        Out[(size_t)(r0 + rb + r) * 256 + c0 + cl] = v;
    }
}

// ---------------------------------------------------------------------------
// K4a: mean over groups of 10 rows of n1 (rows BATCH.. of g_N) -> g_m1 [B,256]
// ---------------------------------------------------------------------------
__global__ void k_mean10()
{
    int b = blockIdx.x, t = threadIdx.x;  // 256 threads
    const float* base = g_N + (size_t)(BATCH + b * F1) * 256 + t;
    float acc = 0.f;
    #pragma unroll
    for (int j = 0; j < F1; j++)
        acc += base[(size_t)j * 256];
    g_m1[(size_t)b * 256 + t] = acc * (1.f / F1);
}

// ---------------------------------------------------------------------------
// K5: per-row L2 normalize (folded as output scale) + pred GEMM [256 -> 50]
// 8 rows per block, 256 threads. (y/||y||) @ Wp == (y @ Wp) / ||y||.
// ---------------------------------------------------------------------------
__global__ void __launch_bounds__(256)
k_norm_pred(const float* __restrict__ Wp, float* __restrict__ out)
{
    __shared__ float Ys[8 * 256];
    __shared__ float inv[8];
    const int tid = threadIdx.x;
    const int r0 = blockIdx.x * 8;

    #pragma unroll
    for (int i = tid; i < 8 * 256; i += 256)
        Ys[i] = g_Y[(size_t)r0 * 256 + i];
    __syncthreads();

    {   // per-row sum of squares: 8 rows x 32 lanes
        int row = tid / 32, lane = tid % 32;
        float s = 0.f;
        #pragma unroll
        for (int k = lane; k < 256; k += 32) {
            float v = Ys[row * 256 + k];
            s += v * v;
        }
        #pragma unroll
        for (int o = 16; o > 0; o >>= 1)
            s += __shfl_xor_sync(0xFFFFFFFFu, s, o);
        if (lane == 0)
            inv[row] = rsqrtf(fmaxf(s, 1e-12f));
    }
    __syncthreads();

    // pred: c = tid%64 (50 active), 4 row-groups of 2 rows
    const int c = tid % 64;
    const int rg = tid / 64;
    if (c < 50) {
        float a0 = 0.f, a1 = 0.f;
        const int rl = rg * 2;
        #pragma unroll 4
        for (int k = 0; k < 256; k++) {
            float w = Wp[k * 50 + c];
            a0 += Ys[rl * 256 + k] * w;
            a1 += Ys[(rl + 1) * 256 + k] * w;
        }
        out[(size_t)(r0 + rl) * 50 + c]     = a0 * inv[rl];
        out[(size_t)(r0 + rl + 1) * 50 + c] = a1 * inv[rl + 1];
    }
}

// ---------------------------------------------------------------------------
extern "C" void kernel_launch(void* const* d_in, const int* in_sizes, int n_in,
                              void* d_out, int out_size)
{
    const float* features = (const float*)d_in[0];
    const int*   adj      = (const int*)d_in[1];
    const int*   batch    = (const int*)d_in[2];   // int32 (JAX x64 disabled)
    const float* ws0      = (const float*)d_in[3];
    const float* wn0      = (const float*)d_in[4];
    const float* ws1      = (const float*)d_in[5];
    const float* wn1      = (const float*)d_in[6];
    const float* wp       = (const float*)d_in[7];
    float*       out      = (float*)d_out;

    // Sampling + aggregation
    k_sample1<<<BATCH, 128>>>(features, adj, batch);
    k_sample2<<<NROWS1, 128>>>(features, adj);

    // Layer 0: all 11264 rows share (ws0, wn0). ReLU.
    // ROWS=16, COLS=64 -> grid (704, 4), 40 KB smem
    k_gemm<128, 64, 16, true, 0><<<dim3(NTOT / 16, 4), 256>>>(ws0, wn0);

    // Layer 1 inputs: n0 = first 1024 rows of g_N; m1 = mean over 10 of n1 rows
    k_mean10<<<BATCH, 256>>>();

    // Layer 1 GEMM (identity act): ROWS=8, COLS=32 -> grid (128, 8), 40 KB smem
    k_gemm<256, 32, 8, false, 1><<<dim3(BATCH / 8, 8), 256>>>(ws1, wn1);

    // L2 normalize + prediction head
    k_norm_pred<<<BATCH / 8, 256>>>(wp, out);
}